// round 7
// baseline (speedup 1.0000x reference)
#include <cuda_runtime.h>
#include <cstdint>
#include <math.h>

#define Bn 2
#define Ln 2048
#define Dn 512
#define Vn 50257
#define NLn 12
#define Kn 5
#define An 128
#define Hn 128
#define BLn (Bn*Ln)          /* 4096 rows */
#define BLD (Bn*Ln*Dn)       /* 2,097,152 */
#define CHK 128              /* recurrence chunks */
#define CLEN 16              /* tokens per chunk */
#define STAGES 4
#define GEMM_SMEM (STAGES * 2 * 128 * 20 * 4)   /* 81920 B */

// ---------------- scratch (device globals: no allocation allowed) ----------
__device__ __align__(16) float g_x[BLD];
__device__ __align__(16) float g_xn[BLD];
__device__ __align__(16) float g_t1[BLD];
__device__ __align__(16) float g_y[BLD];
__device__ __align__(16) float g_g1[BLD];
__device__ __align__(16) float g_xs[Bn*Ln*An];
__device__ __align__(16) float g_hdn[Bn*Ln*Hn];
__device__ __align__(16) float g_pc [Bn*CHK*An];
__device__ __align__(16) float g_pcx[Bn*CHK*An];

__device__ __forceinline__ uint32_t tf32_bits(float x) {
    asm("cvt.rna.tf32.f32 %0, %0;" : "+f"(x));
    return __float_as_uint(x);
}

// ---------------- embedding + rope ----------------------------------------
__global__ void embed_rope_k(const int* __restrict__ tok,
                             const float* __restrict__ emb,
                             float* __restrict__ x) {
    int idx = blockIdx.x * blockDim.x + threadIdx.x;
    if (idx >= BLD) return;
    int d  = idx & (Dn - 1);
    int bl = idx >> 9;
    int l  = bl & (Ln - 1);
    int t  = tok[bl];
    const float* e = emb + (size_t)t * Dn;
    const int half = Dn / 2;
    int fi = (d < half) ? d : d - half;
    float invf = powf(10000.f, -(float)fi / (float)half);
    float ang  = (float)l * invf;
    float s, c;
    sincosf(ang, &s, &c);
    float v = e[d];
    float partner = (d < half) ? -e[d + half] : e[d - half];
    x[idx] = v * c + partner * s;
}

// ---------------- rmsnorm ---------------------------------------------------
__global__ void rmsnorm_k(const float* __restrict__ x,
                          const float* __restrict__ w,
                          float* __restrict__ o) {
    int row = blockIdx.x;
    int t = threadIdx.x;                  // 256 threads
    const float* xr = x + (size_t)row * Dn;
    float a  = xr[t];
    float b2 = xr[t + 256];
    __shared__ float red[256];
    red[t] = a * a + b2 * b2;
    __syncthreads();
    for (int s = 128; s > 0; s >>= 1) {
        if (t < s) red[t] += red[t + s];
        __syncthreads();
    }
    float scale = rsqrtf(red[0] / (float)Dn + 1e-6f);
    o[(size_t)row * Dn + t]       = w[t]       * a  * scale;
    o[(size_t)row * Dn + t + 256] = w[t + 256] * b2 * scale;
}

// ---------------- depthwise dilated conv ------------------------------------
__global__ void dconv_k(const float* __restrict__ xn,
                        const float* __restrict__ dw,
                        const float* __restrict__ db,
                        float* __restrict__ o, int dil) {
    int idx = blockIdx.x * blockDim.x + threadIdx.x;
    if (idx >= BLD) return;
    int d  = idx & (Dn - 1);
    int bl = idx >> 9;
    int l  = bl & (Ln - 1);
    int b  = bl >> 11;
    float s = db[d];
#pragma unroll
    for (int k = 0; k < Kn; k++) {
        int t = l + (k - 2) * dil;
        if (t >= 0 && t < Ln)
            s += dw[d * Kn + k] * xn[(((size_t)(b * Ln + t)) << 9) + d];
    }
    o[idx] = s;
}

// ---------------- recurrence: 3-phase chunked scan ---------------------------
__global__ void recur_part_k(const float* __restrict__ xn,
                             const float* __restrict__ alpha,
                             const float* __restrict__ beta,
                             float* __restrict__ pc) {
    int ch = blockIdx.x & (CHK - 1);
    int b  = blockIdx.x >> 7;
    int a  = threadIdx.x;                 // 128
    float al = alpha[a], be = beta[a];
    const float* xp = xn + ((size_t)(b * Ln + ch * CLEN) << 9) + a;
    float h = 0.f;
#pragma unroll
    for (int i = 0; i < CLEN; i++) h = fmaf(al, h, be * xp[(size_t)i << 9]);
    pc[(b * CHK + ch) * An + a] = h;
}

__global__ void recur_scan_k(const float* __restrict__ pc,
                             const float* __restrict__ alpha,
                             float* __restrict__ pcx) {
    int t = threadIdx.x;                  // 256
    int b = t >> 7;
    int a = t & 127;
    float al = alpha[a];
    float f = al;
#pragma unroll
    for (int q = 0; q < 4; q++) f *= f;   // al^16
    float carry = 0.f;
    for (int ch = 0; ch < CHK; ch++) {
        int idx = (b * CHK + ch) * An + a;
        pcx[idx] = carry;
        carry = fmaf(f, carry, pc[idx]);
    }
}

__global__ void recur_apply_k(const float* __restrict__ xn,
                              const float* __restrict__ alpha,
                              const float* __restrict__ beta,
                              const float* __restrict__ pcx,
                              float* __restrict__ xs) {
    int ch = blockIdx.x & (CHK - 1);
    int b  = blockIdx.x >> 7;
    int a  = threadIdx.x;
    float al = alpha[a], be = beta[a];
    float h = pcx[(b * CHK + ch) * An + a];
    const float* xp = xn + ((size_t)(b * Ln + ch * CLEN) << 9) + a;
    float* op = xs + (size_t)(b * Ln + ch * CLEN) * An + a;
#pragma unroll
    for (int i = 0; i < CLEN; i++) {
        h = fmaf(al, h, be * xp[(size_t)i << 9]);
        op[i * An] = h;
    }
}

// ---------------- tensor-core GEMM -------------------------------------------
// tf32 mma.sync m16n8k8, 128x128 tile, BK=16, 4-stage cp.async, 1 sync/iter.
// EPI 0: C=v
// EPI 1: C=gelu(v)
// EPI 2: C = C + add1 + v                      (up-proj residual)
// EPI 3: C = v + (col<An ? add1[m*An+col] : aux[idx])   (pconv + combine)
// EPI 4: C = aux + sigmoid(add1)*tanh(v)       (w2 + glu -> y2)
__device__ __forceinline__ void cp16(uint32_t dst, const void* src, bool pred) {
    asm volatile("cp.async.cg.shared.global [%0], [%1], 16, %2;\n"
                 :: "r"(dst), "l"(src), "r"(pred ? 16 : 0));
}

template <int EPI, bool SWAP>
__global__ void __launch_bounds__(256)
gemm_tc(const float* __restrict__ A,
        const float* __restrict__ Bw,
        const float* __restrict__ bias,
        const float* __restrict__ add1,
        const float* __restrict__ aux,
        float* __restrict__ C,
        int M, int N, int K) {
    extern __shared__ float smem[];
    float (*As)[128][20] = (float(*)[128][20])smem;
    float (*Bs)[128][20] = (float(*)[128][20])(smem + STAGES * 128 * 20);

    const int tid  = threadIdx.x;
    const int m0   = (SWAP ? blockIdx.x : blockIdx.y) * 128;
    const int n0   = (SWAP ? blockIdx.y : blockIdx.x) * 128;
    const int wid  = tid >> 5;
    const int lane = tid & 31;
    const int wr   = wid >> 2;          // 0..1
    const int wc   = wid & 3;           // 0..3
    const int gid  = lane >> 2;
    const int tig  = lane & 3;
    const int mb   = wr * 64;
    const int nb   = wc * 32;

    const int lr = tid >> 2;            // 0..63
    const int lc = (tid & 3) * 4;       // 0,4,8,12

    float acc[4][4][4];
#pragma unroll
    for (int mt = 0; mt < 4; mt++)
#pragma unroll
        for (int nt = 0; nt < 4; nt++)
#pragma unroll
            for (int r = 0; r < 4; r++) acc[mt][nt][r] = 0.f;

    const int KT = K >> 4;

    auto issue = [&](int kt, int s) {
        int k0 = kt << 4;
        const float* ag = A + (size_t)(m0 + lr) * K + k0 + lc;
        cp16(__cvta_generic_to_shared(&As[s][lr][lc]),      ag,          true);
        cp16(__cvta_generic_to_shared(&As[s][lr + 64][lc]), ag + (size_t)64 * K, true);
        int nrow0 = n0 + lr, nrow1 = n0 + lr + 64;
        const float* bg0 = Bw + (size_t)(nrow0 < N ? nrow0 : 0) * K + k0 + lc;
        const float* bg1 = Bw + (size_t)(nrow1 < N ? nrow1 : 0) * K + k0 + lc;
        cp16(__cvta_generic_to_shared(&Bs[s][lr][lc]),      bg0, nrow0 < N);
        cp16(__cvta_generic_to_shared(&Bs[s][lr + 64][lc]), bg1, nrow1 < N);
    };

    // prologue: fill STAGES-1 stages (one commit group per stage)
#pragma unroll
    for (int p = 0; p < STAGES - 1; p++) {
        if (p < KT) issue(p, p);
        asm volatile("cp.async.commit_group;\n");
    }

    for (int kt = 0; kt < KT; kt++) {
        const int s = kt & (STAGES - 1);
        // at loop top, committed groups = (STAGES-1) + kt; need group kt done
        asm volatile("cp.async.wait_group %0;\n" :: "n"(STAGES - 2));
        __syncthreads();
        // prefetch stage kt+STAGES-1 (overwrites stage kt-1; safe: all warps
        // passed compute(kt-1) to reach the barrier above)
        {
            int kn = kt + STAGES - 1;
            if (kn < KT) issue(kn, kn & (STAGES - 1));
            asm volatile("cp.async.commit_group;\n");
        }

#pragma unroll
        for (int k8 = 0; k8 < 2; k8++) {
            const int kk = k8 * 8;
            uint32_t a[4][4], b[4][2];
#pragma unroll
            for (int mt = 0; mt < 4; mt++) {
                int r = mb + mt * 16 + gid;
                a[mt][0] = tf32_bits(As[s][r][kk + tig]);
                a[mt][1] = tf32_bits(As[s][r + 8][kk + tig]);
                a[mt][2] = tf32_bits(As[s][r][kk + tig + 4]);
                a[mt][3] = tf32_bits(As[s][r + 8][kk + tig + 4]);
            }
#pragma unroll
            for (int nt = 0; nt < 4; nt++) {
                int c = nb + nt * 8 + gid;
                b[nt][0] = tf32_bits(Bs[s][c][kk + tig]);
                b[nt][1] = tf32_bits(Bs[s][c][kk + tig + 4]);
            }
#pragma unroll
            for (int mt = 0; mt < 4; mt++)
#pragma unroll
                for (int nt = 0; nt < 4; nt++) {
                    asm volatile(
                        "mma.sync.aligned.m16n8k8.row.col.f32.tf32.tf32.f32 "
                        "{%0,%1,%2,%3}, {%4,%5,%6,%7}, {%8,%9}, {%0,%1,%2,%3};\n"
                        : "+f"(acc[mt][nt][0]), "+f"(acc[mt][nt][1]),
                          "+f"(acc[mt][nt][2]), "+f"(acc[mt][nt][3])
                        : "r"(a[mt][0]), "r"(a[mt][1]), "r"(a[mt][2]), "r"(a[mt][3]),
                          "r"(b[nt][0]), "r"(b[nt][1]));
                }
        }
    }

    // epilogue
#pragma unroll
    for (int mt = 0; mt < 4; mt++) {
        int row0 = m0 + mb + mt * 16 + gid;
#pragma unroll
        for (int nt = 0; nt < 4; nt++) {
            int col0 = n0 + nb + nt * 8 + tig * 2;
#pragma unroll
            for (int half = 0; half < 2; half++) {
                int rr = row0 + half * 8;
#pragma unroll
                for (int cc = 0; cc < 2; cc++) {
                    int col = col0 + cc;
                    if (col < N) {
                        float v = acc[mt][nt][half * 2 + cc] + (bias ? bias[col] : 0.f);
                        size_t idx = (size_t)rr * N + col;
                        if (EPI == 0) {
                            C[idx] = v;
                        } else if (EPI == 1) {
                            C[idx] = 0.5f * v * (1.f + erff(v * 0.70710678118654752f));
                        } else if (EPI == 2) {
                            C[idx] = C[idx] + add1[idx] + v;
                        } else if (EPI == 3) {
                            float r = (col < An) ? add1[(size_t)rr * An + col]
                                                 : aux[idx];
                            C[idx] = v + r;
                        } else {
                            float gg = add1[idx];
                            C[idx] = aux[idx] +
                                     (1.f / (1.f + expf(-gg))) * tanhf(v);
                        }
                    }
                }
            }
        }
    }
}

// ---------------- host ------------------------------------------------------
extern "C" void kernel_launch(void* const* d_in, const int* in_sizes, int n_in,
                              void* d_out, int out_size) {
    const int*   tokens  = (const int*)  d_in[0];
    const float* emb     = (const float*)d_in[1];
    const float* norm_w  = (const float*)d_in[2];
    const float* dconv_w = (const float*)d_in[3];
    const float* dconv_b = (const float*)d_in[4];
    const float* pconv_w = (const float*)d_in[5];
    const float* pconv_b = (const float*)d_in[6];
    const float* alpha   = (const float*)d_in[7];
    const float* beta    = (const float*)d_in[8];
    const float* w1      = (const float*)d_in[9];
    const float* b1      = (const float*)d_in[10];
    const float* w2      = (const float*)d_in[11];
    const float* b2      = (const float*)d_in[12];
    const float* down_w  = (const float*)d_in[13];
    const float* down_b  = (const float*)d_in[14];
    const float* up_w    = (const float*)d_in[15];
    const float* up_b    = (const float*)d_in[16];
    const float* fnw     = (const float*)d_in[17];
    float* out = (float*)d_out;

    float *x, *xn, *t1, *y, *g1, *xs, *hdn, *pc, *pcx;
    cudaGetSymbolAddress((void**)&x,   g_x);
    cudaGetSymbolAddress((void**)&xn,  g_xn);
    cudaGetSymbolAddress((void**)&t1,  g_t1);
    cudaGetSymbolAddress((void**)&y,   g_y);
    cudaGetSymbolAddress((void**)&g1,  g_g1);
    cudaGetSymbolAddress((void**)&xs,  g_xs);
    cudaGetSymbolAddress((void**)&hdn, g_hdn);
    cudaGetSymbolAddress((void**)&pc,  g_pc);
    cudaGetSymbolAddress((void**)&pcx, g_pcx);

    // allow 80 KB dynamic smem on every gemm instantiation we use
    cudaFuncSetAttribute(gemm_tc<0,false>, cudaFuncAttributeMaxDynamicSharedMemorySize, GEMM_SMEM);
    cudaFuncSetAttribute(gemm_tc<0,true>,  cudaFuncAttributeMaxDynamicSharedMemorySize, GEMM_SMEM);
    cudaFuncSetAttribute(gemm_tc<1,false>, cudaFuncAttributeMaxDynamicSharedMemorySize, GEMM_SMEM);
    cudaFuncSetAttribute(gemm_tc<2,false>, cudaFuncAttributeMaxDynamicSharedMemorySize, GEMM_SMEM);
    cudaFuncSetAttribute(gemm_tc<3,false>, cudaFuncAttributeMaxDynamicSharedMemorySize, GEMM_SMEM);
    cudaFuncSetAttribute(gemm_tc<4,false>, cudaFuncAttributeMaxDynamicSharedMemorySize, GEMM_SMEM);

    const int egrid = (BLD + 255) / 256;

    embed_rope_k<<<egrid, 256>>>(tokens, emb, x);

    for (int i = 0; i < NLn; i++) {
        int dil = 1 << (i % 3);
        rmsnorm_k<<<BLn, 256>>>(x, norm_w + i * Dn, xn);
        dconv_k<<<egrid, 256>>>(xn, dconv_w + (size_t)i * Dn * Kn,
                                dconv_b + i * Dn, t1, dil);
        recur_part_k<<<Bn * CHK, An>>>(xn, alpha + i * An, beta + i * An, pc);
        recur_scan_k<<<1, 256>>>(pc, alpha + i * An, pcx);
        recur_apply_k<<<Bn * CHK, An>>>(xn, alpha + i * An, beta + i * An, pcx, xs);

        dim3 gpw(Dn / 128, BLn / 128);  // (4, 32)
        // pconv + combine fused: y = (t1 @ pw^T + pb) + (col<A ? xs : xn)
        gemm_tc<3,false><<<gpw, 256, GEMM_SMEM>>>(
            t1, pconv_w + (size_t)i * Dn * Dn, pconv_b + i * Dn,
            xs, xn, y, BLn, Dn, Dn);

        gemm_tc<0,false><<<gpw, 256, GEMM_SMEM>>>(
            y, w1 + (size_t)i * Dn * Dn, b1 + i * Dn, nullptr, nullptr,
            g1, BLn, Dn, Dn);
        // w2 + glu fused: y2(t1) = y + sigmoid(g1)*tanh(y@w2^T + b2)
        gemm_tc<4,false><<<gpw, 256, GEMM_SMEM>>>(
            y, w2 + (size_t)i * Dn * Dn, b2 + i * Dn, g1, y,
            t1, BLn, Dn, Dn);

        dim3 gdn(Hn / 128, BLn / 128);  // (1, 32)
        gemm_tc<1,false><<<gdn, 256, GEMM_SMEM>>>(
            t1, down_w + (size_t)i * Hn * Dn, down_b + i * Hn, nullptr, nullptr,
            hdn, BLn, Hn, Dn);
        // x_new = x_old + y2 + (hdn @ up^T + up_b)
        gemm_tc<2,false><<<gdn.x * 0 + dim3(Dn / 128, BLn / 128).x == 0 ? dim3(4,32) : dim3(Dn / 128, BLn / 128), 256, GEMM_SMEM>>>(
            hdn, up_w + (size_t)i * Dn * Hn, up_b + i * Dn, t1, nullptr,
            x, BLn, Dn, Hn);
    }

    rmsnorm_k<<<BLn, 256>>>(x, fnw, xn);
    // logits: SWAP raster (x = M) so concurrent CTAs share emb strips
    dim3 gl(BLn / 128, (Vn + 127) / 128);  // (32, 393)
    gemm_tc<0,true><<<gl, 256, GEMM_SMEM>>>(
        xn, emb, nullptr, nullptr, nullptr, out, BLn, Vn, Dn);
}

// round 8
// speedup vs baseline: 1.5659x; 1.5659x over previous
#include <cuda_runtime.h>
#include <cuda_fp16.h>
#include <cstdint>
#include <math.h>

#define Bn 2
#define Ln 2048
#define Dn 512
#define Vn 50257
#define NLn 12
#define Kn 5
#define An 128
#define Hn 128
#define BLn (Bn*Ln)          /* 4096 rows */
#define BLD (Bn*Ln*Dn)       /* 2,097,152 */
#define CHK 128
#define CLEN 16

// ---------------- scratch (device globals) -----------------------------------
__device__ __align__(16) float  g_x[BLD];
__device__ __align__(16) float  g_xn[BLD];
__device__ __align__(16) float  g_y[BLD];
__device__ __align__(16) float  g_gcat[BLn*2*Dn];     /* w1|w2 concat, 16MB */
__device__ __align__(16) float  g_xs[Bn*Ln*An];
__device__ __align__(16) float  g_pc [Bn*CHK*An];
__device__ __align__(16) float  g_pcx[Bn*CHK*An];
// fp16 activation mirrors
__device__ __align__(16) __half g_t1h[BLD];
__device__ __align__(16) __half g_yh[BLD];
__device__ __align__(16) __half g_hdnh[Bn*Ln*Hn];
__device__ __align__(16) __half g_xnh[BLD];
// fp16 weights
__device__ __align__(16) __half g_embh[Vn*Dn];
__device__ __align__(16) __half g_pwh [NLn*Dn*Dn];
__device__ __align__(16) __half g_w1h [NLn*Dn*Dn];
__device__ __align__(16) __half g_w2h [NLn*Dn*Dn];
__device__ __align__(16) __half g_dnh [NLn*Hn*Dn];
__device__ __align__(16) __half g_uph [NLn*Dn*Hn];

// ---------------- fp32 -> fp16 conversion ------------------------------------
__global__ void f2h_k(const float* __restrict__ src, __half* __restrict__ dst,
                      int n4) {
    int i = blockIdx.x * blockDim.x + threadIdx.x;
    if (i >= n4) return;
    float4 v = ((const float4*)src)[i];
    __half2 lo = __floats2half2_rn(v.x, v.y);
    __half2 hi = __floats2half2_rn(v.z, v.w);
    ((__half2*)dst)[i * 2]     = lo;
    ((__half2*)dst)[i * 2 + 1] = hi;
}

// ---------------- embedding + rope ------------------------------------------
__global__ void embed_rope_k(const int* __restrict__ tok,
                             const float* __restrict__ emb,
                             float* __restrict__ x) {
    int idx = blockIdx.x * blockDim.x + threadIdx.x;
    if (idx >= BLD) return;
    int d  = idx & (Dn - 1);
    int bl = idx >> 9;
    int l  = bl & (Ln - 1);
    int t  = tok[bl];
    const float* e = emb + (size_t)t * Dn;
    const int half = Dn / 2;
    int fi = (d < half) ? d : d - half;
    float invf = powf(10000.f, -(float)fi / (float)half);
    float ang  = (float)l * invf;
    float s, c;
    sincosf(ang, &s, &c);
    float v = e[d];
    float partner = (d < half) ? -e[d + half] : e[d - half];
    x[idx] = v * c + partner * s;
}

// ---------------- rmsnorm (optional fp16 mirror) -----------------------------
__global__ void rmsnorm_k(const float* __restrict__ x,
                          const float* __restrict__ w,
                          float* __restrict__ o,
                          __half* __restrict__ oh) {
    int row = blockIdx.x;
    int t = threadIdx.x;                  // 256 threads
    const float* xr = x + (size_t)row * Dn;
    float a  = xr[t];
    float b2 = xr[t + 256];
    __shared__ float red[256];
    red[t] = a * a + b2 * b2;
    __syncthreads();
    for (int s = 128; s > 0; s >>= 1) {
        if (t < s) red[t] += red[t + s];
        __syncthreads();
    }
    float scale = rsqrtf(red[0] / (float)Dn + 1e-6f);
    float v0 = w[t] * a * scale;
    float v1 = w[t + 256] * b2 * scale;
    if (o) {
        o[(size_t)row * Dn + t]       = v0;
        o[(size_t)row * Dn + t + 256] = v1;
    }
    if (oh) {
        oh[(size_t)row * Dn + t]       = __float2half_rn(v0);
        oh[(size_t)row * Dn + t + 256] = __float2half_rn(v1);
    }
}

// ---------------- depthwise dilated conv -> fp16 -----------------------------
__global__ void dconv_k(const float* __restrict__ xn,
                        const float* __restrict__ dw,
                        const float* __restrict__ db,
                        __half* __restrict__ oh, int dil) {
    int idx = blockIdx.x * blockDim.x + threadIdx.x;
    if (idx >= BLD) return;
    int d  = idx & (Dn - 1);
    int bl = idx >> 9;
    int l  = bl & (Ln - 1);
    int b  = bl >> 11;
    float s = db[d];
#pragma unroll
    for (int k = 0; k < Kn; k++) {
        int t = l + (k - 2) * dil;
        if (t >= 0 && t < Ln)
            s += dw[d * Kn + k] * xn[(((size_t)(b * Ln + t)) << 9) + d];
    }
    oh[idx] = __float2half_rn(s);
}

// ---------------- recurrence: 3-phase chunked scan ---------------------------
__global__ void recur_part_k(const float* __restrict__ xn,
                             const float* __restrict__ alpha,
                             const float* __restrict__ beta,
                             float* __restrict__ pc) {
    int ch = blockIdx.x & (CHK - 1);
    int b  = blockIdx.x >> 7;
    int a  = threadIdx.x;                 // 128
    float al = alpha[a], be = beta[a];
    const float* xp = xn + ((size_t)(b * Ln + ch * CLEN) << 9) + a;
    float h = 0.f;
#pragma unroll
    for (int i = 0; i < CLEN; i++) h = fmaf(al, h, be * xp[(size_t)i << 9]);
    pc[(b * CHK + ch) * An + a] = h;
}

__global__ void recur_scan_k(const float* __restrict__ pc,
                             const float* __restrict__ alpha,
                             float* __restrict__ pcx) {
    int t = threadIdx.x;                  // 256
    int b = t >> 7;
    int a = t & 127;
    float al = alpha[a];
    float f = al;
#pragma unroll
    for (int q = 0; q < 4; q++) f *= f;   // al^16
    float carry = 0.f;
    for (int ch = 0; ch < CHK; ch++) {
        int idx = (b * CHK + ch) * An + a;
        pcx[idx] = carry;
        carry = fmaf(f, carry, pc[idx]);
    }
}

__global__ void recur_apply_k(const float* __restrict__ xn,
                              const float* __restrict__ alpha,
                              const float* __restrict__ beta,
                              const float* __restrict__ pcx,
                              float* __restrict__ xs) {
    int ch = blockIdx.x & (CHK - 1);
    int b  = blockIdx.x >> 7;
    int a  = threadIdx.x;
    float al = alpha[a], be = beta[a];
    float h = pcx[(b * CHK + ch) * An + a];
    const float* xp = xn + ((size_t)(b * Ln + ch * CLEN) << 9) + a;
    float* op = xs + (size_t)(b * Ln + ch * CLEN) * An + a;
#pragma unroll
    for (int i = 0; i < CLEN; i++) {
        h = fmaf(al, h, be * xp[(size_t)i << 9]);
        op[i * An] = h;
    }
}

// ---------------- glu: y += sigmoid(g1)*tanh(g2); yh = fp16(y) ---------------
__global__ void glu_k(const float* __restrict__ gcat,
                      float* __restrict__ y,
                      __half* __restrict__ yh) {
    int idx = blockIdx.x * blockDim.x + threadIdx.x;
    if (idx >= BLD) return;
    int d  = idx & (Dn - 1);
    int bl = idx >> 9;
    float a = gcat[(size_t)bl * (2 * Dn) + d];
    float b = gcat[(size_t)bl * (2 * Dn) + Dn + d];
    float v = y[idx] + (1.f / (1.f + expf(-a))) * tanhf(b);
    y[idx]  = v;
    yh[idx] = __float2half_rn(v);
}

// ---------------- fp16 tensor-core GEMM --------------------------------------
// mma.sync m16n8k16 f16, 128x128 tile, BK=32, 2-stage cp.async (R6-proven).
// B rows n < nsplit from Bw, else Bw2[(n-nsplit)*K] (fused w1|w2).
// EPI 0: C=v            EPI 1: gelu -> Ch (and C if non-null)
// EPI 2: C = C + add1 + v
// EPI 3: C = v + (col<An ? add1[m*An+col] : aux[idx])  (pconv+combine)
__device__ __forceinline__ void cp16(uint32_t dst, const void* src, bool pred) {
    asm volatile("cp.async.cg.shared.global [%0], [%1], 16, %2;\n"
                 :: "r"(dst), "l"(src), "r"(pred ? 16 : 0));
}

template <int EPI>
__global__ void __launch_bounds__(256)
gemm_h(const __half* __restrict__ A,
       const __half* __restrict__ Bw,
       const __half* __restrict__ Bw2,
       const float* __restrict__ bias,
       const float* __restrict__ bias2,
       const float* __restrict__ add1,
       const float* __restrict__ aux,
       float* __restrict__ C,
       __half* __restrict__ Ch,
       int M, int N, int K, int nsplit) {
    // row = 32 halves (16 u32) + 4 u32 pad = 20 u32 (80B) -> conflict-free
    __shared__ uint32_t As[2][128][20];
    __shared__ uint32_t Bs[2][128][20];

    const int tid  = threadIdx.x;
    const int m0   = blockIdx.y * 128;
    const int n0   = blockIdx.x * 128;
    const int wid  = tid >> 5;
    const int lane = tid & 31;
    const int wr   = wid >> 2;
    const int wc   = wid & 3;
    const int gid  = lane >> 2;
    const int tig  = lane & 3;
    const int mb   = wr * 64;
    const int nb   = wc * 32;

    const int lr = tid >> 2;            // 0..63
    const int lc = tid & 3;             // 16B chunk (8 halves)

    float acc[4][4][4];
#pragma unroll
    for (int mt = 0; mt < 4; mt++)
#pragma unroll
        for (int nt = 0; nt < 4; nt++)
#pragma unroll
            for (int r = 0; r < 4; r++) acc[mt][nt][r] = 0.f;

    const int KT = K >> 5;              // BK=32

    auto issue = [&](int kt, int s) {
        int k0 = kt << 5;
        const __half* ag = A + (size_t)(m0 + lr) * K + k0 + lc * 8;
        cp16(__cvta_generic_to_shared(&As[s][lr][lc * 4]),      ag, true);
        cp16(__cvta_generic_to_shared(&As[s][lr + 64][lc * 4]), ag + (size_t)64 * K, true);
        int nrow0 = n0 + lr, nrow1 = n0 + lr + 64;
        const __half* bg0 = (nrow0 < nsplit)
            ? Bw  + (size_t)nrow0 * K + k0 + lc * 8
            : Bw2 + (size_t)(nrow0 - nsplit) * K + k0 + lc * 8;
        const __half* bg1 = (nrow1 < nsplit)
            ? Bw  + (size_t)(nrow1 < N ? nrow1 : 0) * K + k0 + lc * 8
            : Bw2 + (size_t)(nrow1 - nsplit) * K + k0 + lc * 8;
        cp16(__cvta_generic_to_shared(&Bs[s][lr][lc * 4]),      bg0, nrow0 < N);
        cp16(__cvta_generic_to_shared(&Bs[s][lr + 64][lc * 4]), bg1, nrow1 < N);
    };

    issue(0, 0);
    asm volatile("cp.async.commit_group;\n");

    for (int kt = 0; kt < KT; kt++) {
        int s = kt & 1;
        if (kt + 1 < KT) {
            issue(kt + 1, s ^ 1);
            asm volatile("cp.async.commit_group;\n");
            asm volatile("cp.async.wait_group 1;\n");
        } else {
            asm volatile("cp.async.wait_group 0;\n");
        }
        __syncthreads();

#pragma unroll
        for (int k8 = 0; k8 < 2; k8++) {        // two k16 steps
            const int ko = k8 * 8;              // u32 offset
            uint32_t a[4][4], b[4][2];
#pragma unroll
            for (int mt = 0; mt < 4; mt++) {
                int r = mb + mt * 16 + gid;
                a[mt][0] = As[s][r][ko + tig];
                a[mt][1] = As[s][r + 8][ko + tig];
                a[mt][2] = As[s][r][ko + tig + 4];
                a[mt][3] = As[s][r + 8][ko + tig + 4];
            }
#pragma unroll
            for (int nt = 0; nt < 4; nt++) {
                int c = nb + nt * 8 + gid;
                b[nt][0] = Bs[s][c][ko + tig];
                b[nt][1] = Bs[s][c][ko + tig + 4];
            }
#pragma unroll
            for (int mt = 0; mt < 4; mt++)
#pragma unroll
                for (int nt = 0; nt < 4; nt++) {
                    asm volatile(
                        "mma.sync.aligned.m16n8k16.row.col.f32.f16.f16.f32 "
                        "{%0,%1,%2,%3}, {%4,%5,%6,%7}, {%8,%9}, {%0,%1,%2,%3};\n"
                        : "+f"(acc[mt][nt][0]), "+f"(acc[mt][nt][1]),
                          "+f"(acc[mt][nt][2]), "+f"(acc[mt][nt][3])
                        : "r"(a[mt][0]), "r"(a[mt][1]), "r"(a[mt][2]), "r"(a[mt][3]),
                          "r"(b[nt][0]), "r"(b[nt][1]));
                }
        }
        __syncthreads();
    }

    // epilogue
#pragma unroll
    for (int mt = 0; mt < 4; mt++) {
        int row0 = m0 + mb + mt * 16 + gid;
#pragma unroll
        for (int nt = 0; nt < 4; nt++) {
            int col0 = n0 + nb + nt * 8 + tig * 2;
#pragma unroll
            for (int half = 0; half < 2; half++) {
                int rr = row0 + half * 8;
#pragma unroll
                for (int cc = 0; cc < 2; cc++) {
                    int col = col0 + cc;
                    if (col < N) {
                        float bsv = bias ? ((col < nsplit) ? bias[col]
                                                           : bias2[col - nsplit])
                                         : 0.f;
                        float v = acc[mt][nt][half * 2 + cc] + bsv;
                        size_t idx = (size_t)rr * N + col;
                        if (EPI == 0) {
                            C[idx] = v;
                        } else if (EPI == 1) {
                            float g = 0.5f * v * (1.f + erff(v * 0.70710678118654752f));
                            if (C)  C[idx]  = g;
                            if (Ch) Ch[idx] = __float2half_rn(g);
                        } else if (EPI == 2) {
                            C[idx] = C[idx] + add1[idx] + v;
                        } else {
                            float r = (col < An) ? add1[(size_t)rr * An + col]
                                                 : aux[idx];
                            float o = v + r;
                            C[idx]  = o;
                            if (Ch) Ch[idx] = __float2half_rn(o);
                        }
                    }
                }
            }
        }
    }
}

// ---------------- host ------------------------------------------------------
extern "C" void kernel_launch(void* const* d_in, const int* in_sizes, int n_in,
                              void* d_out, int out_size) {
    const int*   tokens  = (const int*)  d_in[0];
    const float* emb     = (const float*)d_in[1];
    const float* norm_w  = (const float*)d_in[2];
    const float* dconv_w = (const float*)d_in[3];
    const float* dconv_b = (const float*)d_in[4];
    const float* pconv_w = (const float*)d_in[5];
    const float* pconv_b = (const float*)d_in[6];
    const float* alpha   = (const float*)d_in[7];
    const float* beta    = (const float*)d_in[8];
    const float* w1      = (const float*)d_in[9];
    const float* b1      = (const float*)d_in[10];
    const float* w2      = (const float*)d_in[11];
    const float* b2      = (const float*)d_in[12];
    const float* down_w  = (const float*)d_in[13];
    const float* down_b  = (const float*)d_in[14];
    const float* up_w    = (const float*)d_in[15];
    const float* up_b    = (const float*)d_in[16];
    const float* fnw     = (const float*)d_in[17];
    float* out = (float*)d_out;

    float *x, *xn, *y, *gcat, *xs, *pc, *pcx;
    __half *t1h, *yh, *hdnh, *xnh, *embh, *pwh, *w1h, *w2h, *dnh, *uph;
    cudaGetSymbolAddress((void**)&x,    g_x);
    cudaGetSymbolAddress((void**)&xn,   g_xn);
    cudaGetSymbolAddress((void**)&y,    g_y);
    cudaGetSymbolAddress((void**)&gcat, g_gcat);
    cudaGetSymbolAddress((void**)&xs,   g_xs);
    cudaGetSymbolAddress((void**)&pc,   g_pc);
    cudaGetSymbolAddress((void**)&pcx,  g_pcx);
    cudaGetSymbolAddress((void**)&t1h,  g_t1h);
    cudaGetSymbolAddress((void**)&yh,   g_yh);
    cudaGetSymbolAddress((void**)&hdnh, g_hdnh);
    cudaGetSymbolAddress((void**)&xnh,  g_xnh);
    cudaGetSymbolAddress((void**)&embh, g_embh);
    cudaGetSymbolAddress((void**)&pwh,  g_pwh);
    cudaGetSymbolAddress((void**)&w1h,  g_w1h);
    cudaGetSymbolAddress((void**)&w2h,  g_w2h);
    cudaGetSymbolAddress((void**)&dnh,  g_dnh);
    cudaGetSymbolAddress((void**)&uph,  g_uph);

    const int egrid = (BLD + 255) / 256;

    // fp16 weight conversion
    {
        int n;
        n = Vn * Dn / 4;        f2h_k<<<(n + 255) / 256, 256>>>(emb,     embh, n);
        n = NLn * Dn * Dn / 4;  f2h_k<<<(n + 255) / 256, 256>>>(pconv_w, pwh,  n);
        n = NLn * Dn * Dn / 4;  f2h_k<<<(n + 255) / 256, 256>>>(w1,      w1h,  n);
        n = NLn * Dn * Dn / 4;  f2h_k<<<(n + 255) / 256, 256>>>(w2,      w2h,  n);
        n = NLn * Hn * Dn / 4;  f2h_k<<<(n + 255) / 256, 256>>>(down_w,  dnh,  n);
        n = NLn * Dn * Hn / 4;  f2h_k<<<(n + 255) / 256, 256>>>(up_w,    uph,  n);
    }

    embed_rope_k<<<egrid, 256>>>(tokens, emb, x);

    for (int i = 0; i < NLn; i++) {
        int dil = 1 << (i % 3);
        rmsnorm_k<<<BLn, 256>>>(x, norm_w + i * Dn, xn, nullptr);
        dconv_k<<<egrid, 256>>>(xn, dconv_w + (size_t)i * Dn * Kn,
                                dconv_b + i * Dn, t1h, dil);
        recur_part_k<<<Bn * CHK, An>>>(xn, alpha + i * An, beta + i * An, pc);
        recur_scan_k<<<1, 256>>>(pc, alpha + i * An, pcx);
        recur_apply_k<<<Bn * CHK, An>>>(xn, alpha + i * An, beta + i * An, pcx, xs);

        dim3 gpw(Dn / 128, BLn / 128);  // (4, 32)
        // pconv + combine: y = pconv(t1) + (col<A ? xs : xn); yh mirror
        gemm_h<3><<<gpw, 256>>>(t1h, pwh + (size_t)i * Dn * Dn, nullptr,
                                pconv_b + i * Dn, nullptr, xs, xn,
                                y, yh, BLn, Dn, Dn, Dn);

        // fused w1|w2: gcat[:, :512]=w1(y), [:,512:]=w2(y)  (256 CTAs)
        dim3 gw12(2 * Dn / 128, BLn / 128);  // (8, 32)
        gemm_h<0><<<gw12, 256>>>(yh, w1h + (size_t)i * Dn * Dn,
                                 w2h + (size_t)i * Dn * Dn,
                                 b1 + i * Dn, b2 + i * Dn, nullptr, nullptr,
                                 gcat, nullptr, BLn, 2 * Dn, Dn, Dn);
        glu_k<<<egrid, 256>>>(gcat, y, yh);

        dim3 gdn(Hn / 128, BLn / 128);  // (1, 32)
        gemm_h<1><<<gdn, 256>>>(yh, dnh + (size_t)i * Hn * Dn, nullptr,
                                down_b + i * Hn, nullptr, nullptr, nullptr,
                                nullptr, hdnh, BLn, Hn, Dn, Hn);
        // x = x + y + up(hdn)
        gemm_h<2><<<gpw, 256>>>(hdnh, uph + (size_t)i * Dn * Hn, nullptr,
                                up_b + i * Dn, nullptr, y, nullptr,
                                x, nullptr, BLn, Dn, Hn, Dn);
    }

    rmsnorm_k<<<BLn, 256>>>(x, fnw, nullptr, xnh);
    dim3 gl((Vn + 127) / 128, BLn / 128);  // (393, 32) — emb fp16 L2-resident
    gemm_h<0><<<gl, 256>>>(xnh, embh, nullptr, nullptr, nullptr, nullptr,
                           nullptr, out, nullptr, BLn, Vn, Dn, Vn);
}

// round 9
// speedup vs baseline: 1.7385x; 1.1102x over previous
#include <cuda_runtime.h>
#include <cuda_fp16.h>
#include <cstdint>
#include <math.h>

#define Bn 2
#define Ln 2048
#define Dn 512
#define Vn 50257
#define NLn 12
#define Kn 5
#define An 128
#define Hn 128
#define BLn (Bn*Ln)
#define BLD (Bn*Ln*Dn)
#define CHK 128
#define CLEN 16

#define SROW 36                                   /* u32 per smem row (64h + pad) */
#define GEMM_SMEM  (2 * 2 * 128 * SROW * 4)       /* 73,728 B  */
#define DUAL_SMEM  (2 * 3 * 128 * SROW * 4)       /* 110,592 B */

// ---------------- scratch (device globals) -----------------------------------
__device__ __align__(16) float  g_x[BLD];
__device__ __align__(16) float  g_xn[BLD];
__device__ __align__(16) float  g_y[BLD];
__device__ __align__(16) float  g_xs[Bn*Ln*An];
__device__ __align__(16) float  g_pc [Bn*CHK*An];
__device__ __align__(16) float  g_pcx[Bn*CHK*An];
// fp16 activation mirrors
__device__ __align__(16) __half g_t1h[BLD];
__device__ __align__(16) __half g_yh[BLD];
__device__ __align__(16) __half g_hdnh[Bn*Ln*Hn];
__device__ __align__(16) __half g_xnh[BLD];
// fp16 weights
__device__ __align__(16) __half g_embh[Vn*Dn];
__device__ __align__(16) __half g_pwh [NLn*Dn*Dn];
__device__ __align__(16) __half g_w1h [NLn*Dn*Dn];
__device__ __align__(16) __half g_w2h [NLn*Dn*Dn];
__device__ __align__(16) __half g_dnh [NLn*Hn*Dn];
__device__ __align__(16) __half g_uph [NLn*Dn*Hn];

// ---------------- fp32 -> fp16 -----------------------------------------------
__global__ void f2h_k(const float* __restrict__ src, __half* __restrict__ dst,
                      int n4) {
    int i = blockIdx.x * blockDim.x + threadIdx.x;
    if (i >= n4) return;
    float4 v = ((const float4*)src)[i];
    ((__half2*)dst)[i * 2]     = __floats2half2_rn(v.x, v.y);
    ((__half2*)dst)[i * 2 + 1] = __floats2half2_rn(v.z, v.w);
}

// ---------------- embedding + rope ------------------------------------------
__global__ void embed_rope_k(const int* __restrict__ tok,
                             const float* __restrict__ emb,
                             float* __restrict__ x) {
    int idx = blockIdx.x * blockDim.x + threadIdx.x;
    if (idx >= BLD) return;
    int d  = idx & (Dn - 1);
    int bl = idx >> 9;
    int l  = bl & (Ln - 1);
    int t  = tok[bl];
    const float* e = emb + (size_t)t * Dn;
    const int half = Dn / 2;
    int fi = (d < half) ? d : d - half;
    float invf = powf(10000.f, -(float)fi / (float)half);
    float ang  = (float)l * invf;
    float s, c;
    sincosf(ang, &s, &c);
    float v = e[d];
    float partner = (d < half) ? -e[d + half] : e[d - half];
    x[idx] = v * c + partner * s;
}

// ---------------- rmsnorm ----------------------------------------------------
__global__ void rmsnorm_k(const float* __restrict__ x,
                          const float* __restrict__ w,
                          float* __restrict__ o,
                          __half* __restrict__ oh) {
    int row = blockIdx.x;
    int t = threadIdx.x;
    const float* xr = x + (size_t)row * Dn;
    float a  = xr[t];
    float b2 = xr[t + 256];
    __shared__ float red[256];
    red[t] = a * a + b2 * b2;
    __syncthreads();
    for (int s = 128; s > 0; s >>= 1) {
        if (t < s) red[t] += red[t + s];
        __syncthreads();
    }
    float scale = rsqrtf(red[0] / (float)Dn + 1e-6f);
    float v0 = w[t] * a * scale;
    float v1 = w[t + 256] * b2 * scale;
    if (o) {
        o[(size_t)row * Dn + t]       = v0;
        o[(size_t)row * Dn + t + 256] = v1;
    }
    if (oh) {
        oh[(size_t)row * Dn + t]       = __float2half_rn(v0);
        oh[(size_t)row * Dn + t + 256] = __float2half_rn(v1);
    }
}

// ---------------- depthwise dilated conv -> fp16 -----------------------------
__global__ void dconv_k(const float* __restrict__ xn,
                        const float* __restrict__ dw,
                        const float* __restrict__ db,
                        __half* __restrict__ oh, int dil) {
    int idx = blockIdx.x * blockDim.x + threadIdx.x;
    if (idx >= BLD) return;
    int d  = idx & (Dn - 1);
    int bl = idx >> 9;
    int l  = bl & (Ln - 1);
    int b  = bl >> 11;
    float s = db[d];
#pragma unroll
    for (int k = 0; k < Kn; k++) {
        int t = l + (k - 2) * dil;
        if (t >= 0 && t < Ln)
            s += dw[d * Kn + k] * xn[(((size_t)(b * Ln + t)) << 9) + d];
    }
    oh[idx] = __float2half_rn(s);
}

// ---------------- recurrence: 3-phase chunked scan ---------------------------
__global__ void recur_part_k(const float* __restrict__ xn,
                             const float* __restrict__ alpha,
                             const float* __restrict__ beta,
                             float* __restrict__ pc) {
    int ch = blockIdx.x & (CHK - 1);
    int b  = blockIdx.x >> 7;
    int a  = threadIdx.x;
    float al = alpha[a], be = beta[a];
    const float* xp = xn + ((size_t)(b * Ln + ch * CLEN) << 9) + a;
    float h = 0.f;
#pragma unroll
    for (int i = 0; i < CLEN; i++) h = fmaf(al, h, be * xp[(size_t)i << 9]);
    pc[(b * CHK + ch) * An + a] = h;
}

__global__ void recur_scan_k(const float* __restrict__ pc,
                             const float* __restrict__ alpha,
                             float* __restrict__ pcx) {
    int t = threadIdx.x;
    int b = t >> 7;
    int a = t & 127;
    float al = alpha[a];
    float f = al;
#pragma unroll
    for (int q = 0; q < 4; q++) f *= f;
    float carry = 0.f;
    for (int ch = 0; ch < CHK; ch++) {
        int idx = (b * CHK + ch) * An + a;
        pcx[idx] = carry;
        carry = fmaf(f, carry, pc[idx]);
    }
}

__global__ void recur_apply_k(const float* __restrict__ xn,
                              const float* __restrict__ alpha,
                              const float* __restrict__ beta,
                              const float* __restrict__ pcx,
                              float* __restrict__ xs) {
    int ch = blockIdx.x & (CHK - 1);
    int b  = blockIdx.x >> 7;
    int a  = threadIdx.x;
    float al = alpha[a], be = beta[a];
    float h = pcx[(b * CHK + ch) * An + a];
    const float* xp = xn + ((size_t)(b * Ln + ch * CLEN) << 9) + a;
    float* op = xs + (size_t)(b * Ln + ch * CLEN) * An + a;
#pragma unroll
    for (int i = 0; i < CLEN; i++) {
        h = fmaf(al, h, be * xp[(size_t)i << 9]);
        op[i * An] = h;
    }
}

// ---------------- helpers ----------------------------------------------------
__device__ __forceinline__ void cp16(uint32_t dst, const void* src, bool pred) {
    asm volatile("cp.async.cg.shared.global [%0], [%1], 16, %2;\n"
                 :: "r"(dst), "l"(src), "r"(pred ? 16 : 0));
}
#define HMMA(acc, a, b)                                                        \
    asm volatile(                                                              \
        "mma.sync.aligned.m16n8k16.row.col.f32.f16.f16.f32 "                   \
        "{%0,%1,%2,%3}, {%4,%5,%6,%7}, {%8,%9}, {%0,%1,%2,%3};\n"              \
        : "+f"(acc[0]), "+f"(acc[1]), "+f"(acc[2]), "+f"(acc[3])               \
        : "r"(a[0]), "r"(a[1]), "r"(a[2]), "r"(a[3]), "r"(b[0]), "r"(b[1]))

// ---------------- fp16 GEMM, 128x128 tile, BK=64, 2-stage --------------------
// EPI 0: C=v   EPI 1: gelu->Ch   EPI 2: C=C+add1+v
// EPI 3: C = v + (col<An ? add1[m*An+col] : aux[idx]);  Ch mirror
template <int EPI>
__global__ void __launch_bounds__(256)
gemm_h(const __half* __restrict__ A,
       const __half* __restrict__ Bw,
       const float* __restrict__ bias,
       const float* __restrict__ add1,
       const float* __restrict__ aux,
       float* __restrict__ C,
       __half* __restrict__ Ch,
       int M, int N, int K) {
    extern __shared__ uint32_t sm[];
    uint32_t (*As)[128][SROW] = (uint32_t(*)[128][SROW])sm;
    uint32_t (*Bs)[128][SROW] = (uint32_t(*)[128][SROW])(sm + 2 * 128 * SROW);

    const int tid  = threadIdx.x;
    const int m0   = blockIdx.y * 128;
    const int n0   = blockIdx.x * 128;
    const int wid  = tid >> 5;
    const int lane = tid & 31;
    const int gid  = lane >> 2;
    const int tig  = lane & 3;
    const int mb   = (wid >> 2) * 64;
    const int nb   = (wid & 3) * 32;

    float acc[4][4][4];
#pragma unroll
    for (int mt = 0; mt < 4; mt++)
#pragma unroll
        for (int nt = 0; nt < 4; nt++)
#pragma unroll
            for (int r = 0; r < 4; r++) acc[mt][nt][r] = 0.f;

    const int KT = K >> 6;                        // BK=64

    auto issue = [&](int kt, int s) {
        int k0 = kt << 6;
#pragma unroll
        for (int j = 0; j < 4; j++) {
            int cid = tid + j * 256;              // 0..1023
            int r   = cid >> 3;
            int col = cid & 7;                    // 16B chunk
            cp16(__cvta_generic_to_shared(&As[s][r][col * 4]),
                 A + (size_t)(m0 + r) * K + k0 + col * 8, true);
            int nr = n0 + r;
            cp16(__cvta_generic_to_shared(&Bs[s][r][col * 4]),
                 Bw + (size_t)(nr < N ? nr : 0) * K + k0 + col * 8, nr < N);
        }
    };

    issue(0, 0);
    asm volatile("cp.async.commit_group;\n");

    for (int kt = 0; kt < KT; kt++) {
        int s = kt & 1;
        if (kt + 1 < KT) {
            issue(kt + 1, s ^ 1);
            asm volatile("cp.async.commit_group;\n");
            asm volatile("cp.async.wait_group 1;\n");
        } else {
            asm volatile("cp.async.wait_group 0;\n");
        }
        __syncthreads();

#pragma unroll
        for (int k8 = 0; k8 < 4; k8++) {          // four k16 steps
            const int ko = k8 * 8;
            uint32_t a[4][4], b[4][2];
#pragma unroll
            for (int mt = 0; mt < 4; mt++) {
                int r = mb + mt * 16 + gid;
                a[mt][0] = As[s][r][ko + tig];
                a[mt][1] = As[s][r + 8][ko + tig];
                a[mt][2] = As[s][r][ko + tig + 4];
                a[mt][3] = As[s][r + 8][ko + tig + 4];
            }
#pragma unroll
            for (int nt = 0; nt < 4; nt++) {
                int c = nb + nt * 8 + gid;
                b[nt][0] = Bs[s][c][ko + tig];
                b[nt][1] = Bs[s][c][ko + tig + 4];
            }
#pragma unroll
            for (int mt = 0; mt < 4; mt++)
#pragma unroll
                for (int nt = 0; nt < 4; nt++)
                    HMMA(acc[mt][nt], a[mt], b[nt]);
        }
        __syncthreads();
    }

#pragma unroll
    for (int mt = 0; mt < 4; mt++) {
        int row0 = m0 + mb + mt * 16 + gid;
#pragma unroll
        for (int nt = 0; nt < 4; nt++) {
            int col0 = n0 + nb + nt * 8 + tig * 2;
#pragma unroll
            for (int hf = 0; hf < 2; hf++) {
                int rr = row0 + hf * 8;
#pragma unroll
                for (int cc = 0; cc < 2; cc++) {
                    int col = col0 + cc;
                    if (col < N) {
                        float v = acc[mt][nt][hf * 2 + cc] + (bias ? bias[col] : 0.f);
                        size_t idx = (size_t)rr * N + col;
                        if (EPI == 0) {
                            C[idx] = v;
                        } else if (EPI == 1) {
                            float g = 0.5f * v * (1.f + erff(v * 0.70710678118654752f));
                            Ch[idx] = __float2half_rn(g);
                        } else if (EPI == 2) {
                            C[idx] = C[idx] + add1[idx] + v;
                        } else {
                            float r = (col < An) ? add1[(size_t)rr * An + col]
                                                 : aux[idx];
                            float o = v + r;
                            C[idx]  = o;
                            Ch[idx] = __float2half_rn(o);
                        }
                    }
                }
            }
        }
    }
}

// ---------------- fused w1|w2 GEMM + GLU -------------------------------------
// y += sigmoid(y@w1^T+b1) * tanh(y@w2^T+b2); dual accumulators, A loaded once.
__global__ void __launch_bounds__(256)
w1w2glu_k(const __half* __restrict__ Ah,
          const __half* __restrict__ W1,
          const __half* __restrict__ W2,
          const float* __restrict__ b1,
          const float* __restrict__ b2,
          float* __restrict__ y,
          __half* __restrict__ yh) {
    extern __shared__ uint32_t sm[];
    uint32_t (*As)[128][SROW]  = (uint32_t(*)[128][SROW])sm;
    uint32_t (*B1s)[128][SROW] = (uint32_t(*)[128][SROW])(sm + 2 * 128 * SROW);
    uint32_t (*B2s)[128][SROW] = (uint32_t(*)[128][SROW])(sm + 4 * 128 * SROW);

    const int tid  = threadIdx.x;
    const int m0   = blockIdx.y * 128;
    const int n0   = blockIdx.x * 128;
    const int wid  = tid >> 5;
    const int lane = tid & 31;
    const int gid  = lane >> 2;
    const int tig  = lane & 3;
    const int mb   = (wid >> 2) * 64;
    const int nb   = (wid & 3) * 32;
    const int K    = Dn;

    float acc1[4][4][4], acc2[4][4][4];
#pragma unroll
    for (int mt = 0; mt < 4; mt++)
#pragma unroll
        for (int nt = 0; nt < 4; nt++)
#pragma unroll
            for (int r = 0; r < 4; r++) { acc1[mt][nt][r] = 0.f; acc2[mt][nt][r] = 0.f; }

    const int KT = K >> 6;                        // 8

    auto issue = [&](int kt, int s) {
        int k0 = kt << 6;
#pragma unroll
        for (int j = 0; j < 4; j++) {
            int cid = tid + j * 256;
            int r   = cid >> 3;
            int col = cid & 7;
            cp16(__cvta_generic_to_shared(&As[s][r][col * 4]),
                 Ah + (size_t)(m0 + r) * K + k0 + col * 8, true);
            cp16(__cvta_generic_to_shared(&B1s[s][r][col * 4]),
                 W1 + (size_t)(n0 + r) * K + k0 + col * 8, true);
            cp16(__cvta_generic_to_shared(&B2s[s][r][col * 4]),
                 W2 + (size_t)(n0 + r) * K + k0 + col * 8, true);
        }
    };

    issue(0, 0);
    asm volatile("cp.async.commit_group;\n");

    for (int kt = 0; kt < KT; kt++) {
        int s = kt & 1;
        if (kt + 1 < KT) {
            issue(kt + 1, s ^ 1);
            asm volatile("cp.async.commit_group;\n");
            asm volatile("cp.async.wait_group 1;\n");
        } else {
            asm volatile("cp.async.wait_group 0;\n");
        }
        __syncthreads();

#pragma unroll
        for (int k8 = 0; k8 < 4; k8++) {
            const int ko = k8 * 8;
            uint32_t a[4][4], b1r[4][2], b2r[4][2];
#pragma unroll
            for (int mt = 0; mt < 4; mt++) {
                int r = mb + mt * 16 + gid;
                a[mt][0] = As[s][r][ko + tig];
                a[mt][1] = As[s][r + 8][ko + tig];
                a[mt][2] = As[s][r][ko + tig + 4];
                a[mt][3] = As[s][r + 8][ko + tig + 4];
            }
#pragma unroll
            for (int nt = 0; nt < 4; nt++) {
                int c = nb + nt * 8 + gid;
                b1r[nt][0] = B1s[s][c][ko + tig];
                b1r[nt][1] = B1s[s][c][ko + tig + 4];
                b2r[nt][0] = B2s[s][c][ko + tig];
                b2r[nt][1] = B2s[s][c][ko + tig + 4];
            }
#pragma unroll
            for (int mt = 0; mt < 4; mt++)
#pragma unroll
                for (int nt = 0; nt < 4; nt++) {
                    HMMA(acc1[mt][nt], a[mt], b1r[nt]);
                    HMMA(acc2[mt][nt], a[mt], b2r[nt]);
                }
        }
        __syncthreads();
    }

#pragma unroll
    for (int mt = 0; mt < 4; mt++) {
        int row0 = m0 + mb + mt * 16 + gid;
#pragma unroll
        for (int nt = 0; nt < 4; nt++) {
            int col0 = n0 + nb + nt * 8 + tig * 2;
#pragma unroll
            for (int hf = 0; hf < 2; hf++) {
                int rr = row0 + hf * 8;
#pragma unroll
                for (int cc = 0; cc < 2; cc++) {
                    int col = col0 + cc;
                    float v1 = acc1[mt][nt][hf * 2 + cc] + b1[col];
                    float v2 = acc2[mt][nt][hf * 2 + cc] + b2[col];
                    size_t idx = (size_t)rr * Dn + col;
                    float o = y[idx] + (1.f / (1.f + expf(-v1))) * tanhf(v2);
                    y[idx]  = o;
                    yh[idx] = __float2half_rn(o);
                }
            }
        }
    }
}

// ---------------- host ------------------------------------------------------
extern "C" void kernel_launch(void* const* d_in, const int* in_sizes, int n_in,
                              void* d_out, int out_size) {
    const int*   tokens  = (const int*)  d_in[0];
    const float* emb     = (const float*)d_in[1];
    const float* norm_w  = (const float*)d_in[2];
    const float* dconv_w = (const float*)d_in[3];
    const float* dconv_b = (const float*)d_in[4];
    const float* pconv_w = (const float*)d_in[5];
    const float* pconv_b = (const float*)d_in[6];
    const float* alpha   = (const float*)d_in[7];
    const float* beta    = (const float*)d_in[8];
    const float* w1      = (const float*)d_in[9];
    const float* b1      = (const float*)d_in[10];
    const float* w2      = (const float*)d_in[11];
    const float* b2      = (const float*)d_in[12];
    const float* down_w  = (const float*)d_in[13];
    const float* down_b  = (const float*)d_in[14];
    const float* up_w    = (const float*)d_in[15];
    const float* up_b    = (const float*)d_in[16];
    const float* fnw     = (const float*)d_in[17];
    float* out = (float*)d_out;

    float *x, *xn, *y, *xs, *pc, *pcx;
    __half *t1h, *yh, *hdnh, *xnh, *embh, *pwh, *w1h, *w2h, *dnh, *uph;
    cudaGetSymbolAddress((void**)&x,    g_x);
    cudaGetSymbolAddress((void**)&xn,   g_xn);
    cudaGetSymbolAddress((void**)&y,    g_y);
    cudaGetSymbolAddress((void**)&xs,   g_xs);
    cudaGetSymbolAddress((void**)&pc,   g_pc);
    cudaGetSymbolAddress((void**)&pcx,  g_pcx);
    cudaGetSymbolAddress((void**)&t1h,  g_t1h);
    cudaGetSymbolAddress((void**)&yh,   g_yh);
    cudaGetSymbolAddress((void**)&hdnh, g_hdnh);
    cudaGetSymbolAddress((void**)&xnh,  g_xnh);
    cudaGetSymbolAddress((void**)&embh, g_embh);
    cudaGetSymbolAddress((void**)&pwh,  g_pwh);
    cudaGetSymbolAddress((void**)&w1h,  g_w1h);
    cudaGetSymbolAddress((void**)&w2h,  g_w2h);
    cudaGetSymbolAddress((void**)&dnh,  g_dnh);
    cudaGetSymbolAddress((void**)&uph,  g_uph);

    cudaFuncSetAttribute(gemm_h<0>, cudaFuncAttributeMaxDynamicSharedMemorySize, GEMM_SMEM);
    cudaFuncSetAttribute(gemm_h<1>, cudaFuncAttributeMaxDynamicSharedMemorySize, GEMM_SMEM);
    cudaFuncSetAttribute(gemm_h<2>, cudaFuncAttributeMaxDynamicSharedMemorySize, GEMM_SMEM);
    cudaFuncSetAttribute(gemm_h<3>, cudaFuncAttributeMaxDynamicSharedMemorySize, GEMM_SMEM);
    cudaFuncSetAttribute(w1w2glu_k, cudaFuncAttributeMaxDynamicSharedMemorySize, DUAL_SMEM);

    const int egrid = (BLD + 255) / 256;

    {
        int n;
        n = Vn * Dn / 4;        f2h_k<<<(n + 255) / 256, 256>>>(emb,     embh, n);
        n = NLn * Dn * Dn / 4;  f2h_k<<<(n + 255) / 256, 256>>>(pconv_w, pwh,  n);
        n = NLn * Dn * Dn / 4;  f2h_k<<<(n + 255) / 256, 256>>>(w1,      w1h,  n);
        n = NLn * Dn * Dn / 4;  f2h_k<<<(n + 255) / 256, 256>>>(w2,      w2h,  n);
        n = NLn * Hn * Dn / 4;  f2h_k<<<(n + 255) / 256, 256>>>(down_w,  dnh,  n);
        n = NLn * Dn * Hn / 4;  f2h_k<<<(n + 255) / 256, 256>>>(up_w,    uph,  n);
    }

    embed_rope_k<<<egrid, 256>>>(tokens, emb, x);

    for (int i = 0; i < NLn; i++) {
        int dil = 1 << (i % 3);
        rmsnorm_k<<<BLn, 256>>>(x, norm_w + i * Dn, xn, nullptr);
        dconv_k<<<egrid, 256>>>(xn, dconv_w + (size_t)i * Dn * Kn,
                                dconv_b + i * Dn, t1h, dil);
        recur_part_k<<<Bn * CHK, An>>>(xn, alpha + i * An, beta + i * An, pc);
        recur_scan_k<<<1, 256>>>(pc, alpha + i * An, pcx);
        recur_apply_k<<<Bn * CHK, An>>>(xn, alpha + i * An, beta + i * An, pcx, xs);

        dim3 gpw(Dn / 128, BLn / 128);  // (4, 32)
        gemm_h<3><<<gpw, 256, GEMM_SMEM>>>(
            t1h, pwh + (size_t)i * Dn * Dn, pconv_b + i * Dn,
            xs, xn, y, yh, BLn, Dn, Dn);

        w1w2glu_k<<<gpw, 256, DUAL_SMEM>>>(
            yh, w1h + (size_t)i * Dn * Dn, w2h + (size_t)i * Dn * Dn,
            b1 + i * Dn, b2 + i * Dn, y, yh);

        dim3 gdn(Hn / 128, BLn / 128);  // (1, 32)
        gemm_h<1><<<gdn, 256, GEMM_SMEM>>>(
            yh, dnh + (size_t)i * Hn * Dn, down_b + i * Hn,
            nullptr, nullptr, nullptr, hdnh, BLn, Hn, Dn);

        gemm_h<2><<<gpw, 256, GEMM_SMEM>>>(
            hdnh, uph + (size_t)i * Dn * Hn, up_b + i * Dn,
            y, nullptr, x, nullptr, BLn, Dn, Hn);
    }

    rmsnorm_k<<<BLn, 256>>>(x, fnw, nullptr, xnh);
    dim3 gl((Vn + 127) / 128, BLn / 128);  // (393, 32)
    gemm_h<0><<<gl, 256, GEMM_SMEM>>>(
        xnh, embh, nullptr, nullptr, nullptr, out, nullptr, BLn, Vn, Dn);
}

// round 10
// speedup vs baseline: 1.7819x; 1.0250x over previous
#include <cuda_runtime.h>
#include <cuda_fp16.h>
#include <cstdint>
#include <math.h>

#define Bn 2
#define Ln 2048
#define Dn 512
#define Vn 50257
#define NLn 12
#define Kn 5
#define An 128
#define Hn 128
#define BLn (Bn*Ln)
#define BLD (Bn*Ln*Dn)
#define CHK 128
#define CLEN 16

#define SROW 36                                   /* u32 per smem row (64h + pad) */
#define GEMM_SMEM  (2 * 2 * 128 * SROW * 4)       /* 73,728 B  */
#define DUAL_SMEM  (2 * 3 * 128 * SROW * 4)       /* 110,592 B */

// ---------------- scratch (device globals) -----------------------------------
__device__ __align__(16) float  g_x[BLD];
__device__ __align__(16) float  g_xn[BLD];
__device__ __align__(16) float  g_y[BLD];
__device__ __align__(16) float  g_xs[Bn*Ln*An];
__device__ __align__(16) float  g_pc [Bn*CHK*An];
__device__ __align__(16) float  g_pcx[Bn*CHK*An];
__device__ __align__(16) __half g_t1h[BLD];
__device__ __align__(16) __half g_yh[BLD];
__device__ __align__(16) __half g_hdnh[Bn*Ln*Hn];
__device__ __align__(16) __half g_xnh[BLD];
__device__ __align__(16) __half g_embh[Vn*Dn];
__device__ __align__(16) __half g_pwh [NLn*Dn*Dn];
__device__ __align__(16) __half g_w1h [NLn*Dn*Dn];
__device__ __align__(16) __half g_w2h [NLn*Dn*Dn];
__device__ __align__(16) __half g_dnh [NLn*Hn*Dn];
__device__ __align__(16) __half g_uph [NLn*Dn*Hn];

// ---------------- fp32 -> fp16 -----------------------------------------------
__global__ void f2h_k(const float* __restrict__ src, __half* __restrict__ dst,
                      int n4) {
    int i = blockIdx.x * blockDim.x + threadIdx.x;
    if (i >= n4) return;
    float4 v = ((const float4*)src)[i];
    ((__half2*)dst)[i * 2]     = __floats2half2_rn(v.x, v.y);
    ((__half2*)dst)[i * 2 + 1] = __floats2half2_rn(v.z, v.w);
}

// ---------------- embedding + rope ------------------------------------------
__global__ void embed_rope_k(const int* __restrict__ tok,
                             const float* __restrict__ emb,
                             float* __restrict__ x) {
    int idx = blockIdx.x * blockDim.x + threadIdx.x;
    if (idx >= BLD) return;
    int d  = idx & (Dn - 1);
    int bl = idx >> 9;
    int l  = bl & (Ln - 1);
    int t  = tok[bl];
    const float* e = emb + (size_t)t * Dn;
    const int half = Dn / 2;
    int fi = (d < half) ? d : d - half;
    float invf = powf(10000.f, -(float)fi / (float)half);
    float ang  = (float)l * invf;
    float s, c;
    sincosf(ang, &s, &c);
    float v = e[d];
    float partner = (d < half) ? -e[d + half] : e[d - half];
    x[idx] = v * c + partner * s;
}

// ---------------- rmsnorm ----------------------------------------------------
__global__ void rmsnorm_k(const float* __restrict__ x,
                          const float* __restrict__ w,
                          float* __restrict__ o,
                          __half* __restrict__ oh) {
    int row = blockIdx.x;
    int t = threadIdx.x;
    const float* xr = x + (size_t)row * Dn;
    float a  = xr[t];
    float b2 = xr[t + 256];
    __shared__ float red[256];
    red[t] = a * a + b2 * b2;
    __syncthreads();
    for (int s = 128; s > 0; s >>= 1) {
        if (t < s) red[t] += red[t + s];
        __syncthreads();
    }
    float scale = rsqrtf(red[0] / (float)Dn + 1e-6f);
    float v0 = w[t] * a * scale;
    float v1 = w[t + 256] * b2 * scale;
    if (o) {
        o[(size_t)row * Dn + t]       = v0;
        o[(size_t)row * Dn + t + 256] = v1;
    }
    if (oh) {
        oh[(size_t)row * Dn + t]       = __float2half_rn(v0);
        oh[(size_t)row * Dn + t + 256] = __float2half_rn(v1);
    }
}

// ---------------- depthwise dilated conv -> fp16 -----------------------------
__global__ void dconv_k(const float* __restrict__ xn,
                        const float* __restrict__ dw,
                        const float* __restrict__ db,
                        __half* __restrict__ oh, int dil) {
    int idx = blockIdx.x * blockDim.x + threadIdx.x;
    if (idx >= BLD) return;
    int d  = idx & (Dn - 1);
    int bl = idx >> 9;
    int l  = bl & (Ln - 1);
    int b  = bl >> 11;
    float s = db[d];
#pragma unroll
    for (int k = 0; k < Kn; k++) {
        int t = l + (k - 2) * dil;
        if (t >= 0 && t < Ln)
            s += dw[d * Kn + k] * xn[(((size_t)(b * Ln + t)) << 9) + d];
    }
    oh[idx] = __float2half_rn(s);
}

// ---------------- recurrence: 3-phase chunked scan ---------------------------
__global__ void recur_part_k(const float* __restrict__ xn,
                             const float* __restrict__ alpha,
                             const float* __restrict__ beta,
                             float* __restrict__ pc) {
    int ch = blockIdx.x & (CHK - 1);
    int b  = blockIdx.x >> 7;
    int a  = threadIdx.x;
    float al = alpha[a], be = beta[a];
    const float* xp = xn + ((size_t)(b * Ln + ch * CLEN) << 9) + a;
    float h = 0.f;
#pragma unroll
    for (int i = 0; i < CLEN; i++) h = fmaf(al, h, be * xp[(size_t)i << 9]);
    pc[(b * CHK + ch) * An + a] = h;
}

__global__ void recur_scan_k(const float* __restrict__ pc,
                             const float* __restrict__ alpha,
                             float* __restrict__ pcx) {
    int t = threadIdx.x;
    int b = t >> 7;
    int a = t & 127;
    float al = alpha[a];
    float f = al;
#pragma unroll
    for (int q = 0; q < 4; q++) f *= f;
    float carry = 0.f;
    for (int ch = 0; ch < CHK; ch++) {
        int idx = (b * CHK + ch) * An + a;
        pcx[idx] = carry;
        carry = fmaf(f, carry, pc[idx]);
    }
}

__global__ void recur_apply_k(const float* __restrict__ xn,
                              const float* __restrict__ alpha,
                              const float* __restrict__ beta,
                              const float* __restrict__ pcx,
                              float* __restrict__ xs) {
    int ch = blockIdx.x & (CHK - 1);
    int b  = blockIdx.x >> 7;
    int a  = threadIdx.x;
    float al = alpha[a], be = beta[a];
    float h = pcx[(b * CHK + ch) * An + a];
    const float* xp = xn + ((size_t)(b * Ln + ch * CLEN) << 9) + a;
    float* op = xs + (size_t)(b * Ln + ch * CLEN) * An + a;
#pragma unroll
    for (int i = 0; i < CLEN; i++) {
        h = fmaf(al, h, be * xp[(size_t)i << 9]);
        op[i * An] = h;
    }
}

// ---------------- helpers ----------------------------------------------------
__device__ __forceinline__ void cp16(uint32_t dst, const void* src, bool pred) {
    asm volatile("cp.async.cg.shared.global [%0], [%1], 16, %2;\n"
                 :: "r"(dst), "l"(src), "r"(pred ? 16 : 0));
}
#define HMMA(acc, a, b)                                                        \
    asm volatile(                                                              \
        "mma.sync.aligned.m16n8k16.row.col.f32.f16.f16.f32 "                   \
        "{%0,%1,%2,%3}, {%4,%5,%6,%7}, {%8,%9}, {%0,%1,%2,%3};\n"              \
        : "+f"(acc[0]), "+f"(acc[1]), "+f"(acc[2]), "+f"(acc[3])               \
        : "r"(a[0]), "r"(a[1]), "r"(a[2]), "r"(a[3]), "r"(b[0]), "r"(b[1]))
#define LDSM4(r0, r1, r2, r3, addr)                                            \
    asm volatile("ldmatrix.sync.aligned.m8n8.x4.shared.b16 {%0,%1,%2,%3}, [%4];" \
                 : "=r"(r0), "=r"(r1), "=r"(r2), "=r"(r3) : "r"(addr))

// ---------------- fp16 GEMM, 128x128 tile, BK=64, 2-stage, ldmatrix ----------
// EPI 0: C=v   EPI 1: gelu->Ch   EPI 2: C=C+add1+v
// EPI 3: C = v + (col<An ? add1[m*An+col] : aux[idx]);  Ch mirror
template <int EPI>
__global__ void __launch_bounds__(256)
gemm_h(const __half* __restrict__ A,
       const __half* __restrict__ Bw,
       const float* __restrict__ bias,
       const float* __restrict__ add1,
       const float* __restrict__ aux,
       float* __restrict__ C,
       __half* __restrict__ Ch,
       int M, int N, int K) {
    extern __shared__ uint32_t sm[];
    const uint32_t sbase = (uint32_t)__cvta_generic_to_shared(sm);
    const uint32_t bbase = sbase + 2 * 128 * SROW * 4;

    const int tid  = threadIdx.x;
    const int m0   = blockIdx.y * 128;
    const int n0   = blockIdx.x * 128;
    const int wid  = tid >> 5;
    const int lane = tid & 31;
    const int gid  = lane >> 2;
    const int tig  = lane & 3;
    const int mb   = (wid >> 2) * 64;
    const int nb   = (wid & 3) * 32;

    // ldmatrix per-lane offsets (bytes)
    const uint32_t aoff = (((uint32_t)(lane & 15)) * SROW + ((lane >> 4) & 1) * 4) * 4;
    const uint32_t boff = (((uint32_t)((lane & 7) + ((lane >> 4) & 1) * 8)) * SROW
                           + ((lane >> 3) & 1) * 4) * 4;

    float acc[4][4][4];
#pragma unroll
    for (int mt = 0; mt < 4; mt++)
#pragma unroll
        for (int nt = 0; nt < 4; nt++)
#pragma unroll
            for (int r = 0; r < 4; r++) acc[mt][nt][r] = 0.f;

    const int KT = K >> 6;                        // BK=64

    auto issue = [&](int kt, int s) {
        int k0 = kt << 6;
#pragma unroll
        for (int j = 0; j < 4; j++) {
            int cid = tid + j * 256;
            int r   = cid >> 3;
            int col = cid & 7;
            cp16(sbase + ((s * 128 + r) * SROW + col * 4) * 4,
                 A + (size_t)(m0 + r) * K + k0 + col * 8, true);
            int nr = n0 + r;
            cp16(bbase + ((s * 128 + r) * SROW + col * 4) * 4,
                 Bw + (size_t)(nr < N ? nr : 0) * K + k0 + col * 8, nr < N);
        }
    };

    issue(0, 0);
    asm volatile("cp.async.commit_group;\n");

    for (int kt = 0; kt < KT; kt++) {
        int s = kt & 1;
        if (kt + 1 < KT) {
            issue(kt + 1, s ^ 1);
            asm volatile("cp.async.commit_group;\n");
            asm volatile("cp.async.wait_group 1;\n");
        } else {
            asm volatile("cp.async.wait_group 0;\n");
        }
        __syncthreads();

        const uint32_t as0 = sbase + (uint32_t)(s * 128 * SROW * 4) + aoff;
        const uint32_t bs0 = bbase + (uint32_t)(s * 128 * SROW * 4) + boff;
#pragma unroll
        for (int k8 = 0; k8 < 4; k8++) {
            const uint32_t ko4 = (uint32_t)(k8 * 8) * 4;  // k16 step (8 u32)
            uint32_t a[4][4], b[4][2];
#pragma unroll
            for (int mt = 0; mt < 4; mt++)
                LDSM4(a[mt][0], a[mt][1], a[mt][2], a[mt][3],
                      as0 + (uint32_t)((mb + mt * 16) * SROW * 4) + ko4);
#pragma unroll
            for (int p = 0; p < 2; p++)
                LDSM4(b[2*p][0], b[2*p][1], b[2*p+1][0], b[2*p+1][1],
                      bs0 + (uint32_t)((nb + p * 16) * SROW * 4) + ko4);
#pragma unroll
            for (int mt = 0; mt < 4; mt++)
#pragma unroll
                for (int nt = 0; nt < 4; nt++)
                    HMMA(acc[mt][nt], a[mt], b[nt]);
        }
        __syncthreads();
    }

#pragma unroll
    for (int mt = 0; mt < 4; mt++) {
        int row0 = m0 + mb + mt * 16 + gid;
#pragma unroll
        for (int nt = 0; nt < 4; nt++) {
            int col0 = n0 + nb + nt * 8 + tig * 2;
#pragma unroll
            for (int hf = 0; hf < 2; hf++) {
                int rr = row0 + hf * 8;
#pragma unroll
                for (int cc = 0; cc < 2; cc++) {
                    int col = col0 + cc;
                    if (col < N) {
                        float v = acc[mt][nt][hf * 2 + cc] + (bias ? bias[col] : 0.f);
                        size_t idx = (size_t)rr * N + col;
                        if (EPI == 0) {
                            C[idx] = v;
                        } else if (EPI == 1) {
                            float g = 0.5f * v * (1.f + erff(v * 0.70710678118654752f));
                            Ch[idx] = __float2half_rn(g);
                        } else if (EPI == 2) {
                            C[idx] = C[idx] + add1[idx] + v;
                        } else {
                            float r = (col < An) ? add1[(size_t)rr * An + col]
                                                 : aux[idx];
                            float o = v + r;
                            C[idx]  = o;
                            Ch[idx] = __float2half_rn(o);
                        }
                    }
                }
            }
        }
    }
}

// ---------------- fused w1|w2 GEMM + GLU (ldmatrix) --------------------------
__global__ void __launch_bounds__(256)
w1w2glu_k(const __half* __restrict__ Ah,
          const __half* __restrict__ W1,
          const __half* __restrict__ W2,
          const float* __restrict__ b1,
          const float* __restrict__ b2,
          float* __restrict__ y,
          __half* __restrict__ yh) {
    extern __shared__ uint32_t sm[];
    const uint32_t sbase  = (uint32_t)__cvta_generic_to_shared(sm);
    const uint32_t b1base = sbase + 2 * 128 * SROW * 4;
    const uint32_t b2base = sbase + 4 * 128 * SROW * 4;

    const int tid  = threadIdx.x;
    const int m0   = blockIdx.y * 128;
    const int n0   = blockIdx.x * 128;
    const int wid  = tid >> 5;
    const int lane = tid & 31;
    const int gid  = lane >> 2;
    const int tig  = lane & 3;
    const int mb   = (wid >> 2) * 64;
    const int nb   = (wid & 3) * 32;
    const int K    = Dn;

    const uint32_t aoff = (((uint32_t)(lane & 15)) * SROW + ((lane >> 4) & 1) * 4) * 4;
    const uint32_t boff = (((uint32_t)((lane & 7) + ((lane >> 4) & 1) * 8)) * SROW
                           + ((lane >> 3) & 1) * 4) * 4;

    float acc1[4][4][4], acc2[4][4][4];
#pragma unroll
    for (int mt = 0; mt < 4; mt++)
#pragma unroll
        for (int nt = 0; nt < 4; nt++)
#pragma unroll
            for (int r = 0; r < 4; r++) { acc1[mt][nt][r] = 0.f; acc2[mt][nt][r] = 0.f; }

    const int KT = K >> 6;

    auto issue = [&](int kt, int s) {
        int k0 = kt << 6;
#pragma unroll
        for (int j = 0; j < 4; j++) {
            int cid = tid + j * 256;
            int r   = cid >> 3;
            int col = cid & 7;
            uint32_t so = ((s * 128 + r) * SROW + col * 4) * 4;
            cp16(sbase  + so, Ah + (size_t)(m0 + r) * K + k0 + col * 8, true);
            cp16(b1base + so, W1 + (size_t)(n0 + r) * K + k0 + col * 8, true);
            cp16(b2base + so, W2 + (size_t)(n0 + r) * K + k0 + col * 8, true);
        }
    };

    issue(0, 0);
    asm volatile("cp.async.commit_group;\n");

    for (int kt = 0; kt < KT; kt++) {
        int s = kt & 1;
        if (kt + 1 < KT) {
            issue(kt + 1, s ^ 1);
            asm volatile("cp.async.commit_group;\n");
            asm volatile("cp.async.wait_group 1;\n");
        } else {
            asm volatile("cp.async.wait_group 0;\n");
        }
        __syncthreads();

        const uint32_t as0  = sbase  + (uint32_t)(s * 128 * SROW * 4) + aoff;
        const uint32_t b1s0 = b1base + (uint32_t)(s * 128 * SROW * 4) + boff;
        const uint32_t b2s0 = b2base + (uint32_t)(s * 128 * SROW * 4) + boff;
#pragma unroll
        for (int k8 = 0; k8 < 4; k8++) {
            const uint32_t ko4 = (uint32_t)(k8 * 8) * 4;
            uint32_t a[4][4], br1[4][2], br2[4][2];
#pragma unroll
            for (int mt = 0; mt < 4; mt++)
                LDSM4(a[mt][0], a[mt][1], a[mt][2], a[mt][3],
                      as0 + (uint32_t)((mb + mt * 16) * SROW * 4) + ko4);
#pragma unroll
            for (int p = 0; p < 2; p++) {
                LDSM4(br1[2*p][0], br1[2*p][1], br1[2*p+1][0], br1[2*p+1][1],
                      b1s0 + (uint32_t)((nb + p * 16) * SROW * 4) + ko4);
                LDSM4(br2[2*p][0], br2[2*p][1], br2[2*p+1][0], br2[2*p+1][1],
                      b2s0 + (uint32_t)((nb + p * 16) * SROW * 4) + ko4);
            }
#pragma unroll
            for (int mt = 0; mt < 4; mt++)
#pragma unroll
                for (int nt = 0; nt < 4; nt++) {
                    HMMA(acc1[mt][nt], a[mt], br1[nt]);
                    HMMA(acc2[mt][nt], a[mt], br2[nt]);
                }
        }
        __syncthreads();
    }

#pragma unroll
    for (int mt = 0; mt < 4; mt++) {
        int row0 = m0 + mb + mt * 16 + gid;
#pragma unroll
        for (int nt = 0; nt < 4; nt++) {
            int col0 = n0 + nb + nt * 8 + tig * 2;
#pragma unroll
            for (int hf = 0; hf < 2; hf++) {
                int rr = row0 + hf * 8;
#pragma unroll
                for (int cc = 0; cc < 2; cc++) {
                    int col = col0 + cc;
                    float v1 = acc1[mt][nt][hf * 2 + cc] + b1[col];
                    float v2 = acc2[mt][nt][hf * 2 + cc] + b2[col];
                    size_t idx = (size_t)rr * Dn + col;
                    float o = y[idx] + (1.f / (1.f + expf(-v1))) * tanhf(v2);
                    y[idx]  = o;
                    yh[idx] = __float2half_rn(o);
                }
            }
        }
    }
}

// ---------------- host ------------------------------------------------------
extern "C" void kernel_launch(void* const* d_in, const int* in_sizes, int n_in,
                              void* d_out, int out_size) {
    const int*   tokens  = (const int*)  d_in[0];
    const float* emb     = (const float*)d_in[1];
    const float* norm_w  = (const float*)d_in[2];
    const float* dconv_w = (const float*)d_in[3];
    const float* dconv_b = (const float*)d_in[4];
    const float* pconv_w = (const float*)d_in[5];
    const float* pconv_b = (const float*)d_in[6];
    const float* alpha   = (const float*)d_in[7];
    const float* beta    = (const float*)d_in[8];
    const float* w1      = (const float*)d_in[9];
    const float* b1      = (const float*)d_in[10];
    const float* w2      = (const float*)d_in[11];
    const float* b2      = (const float*)d_in[12];
    const float* down_w  = (const float*)d_in[13];
    const float* down_b  = (const float*)d_in[14];
    const float* up_w    = (const float*)d_in[15];
    const float* up_b    = (const float*)d_in[16];
    const float* fnw     = (const float*)d_in[17];
    float* out = (float*)d_out;

    float *x, *xn, *y, *xs, *pc, *pcx;
    __half *t1h, *yh, *hdnh, *xnh, *embh, *pwh, *w1h, *w2h, *dnh, *uph;
    cudaGetSymbolAddress((void**)&x,    g_x);
    cudaGetSymbolAddress((void**)&xn,   g_xn);
    cudaGetSymbolAddress((void**)&y,    g_y);
    cudaGetSymbolAddress((void**)&xs,   g_xs);
    cudaGetSymbolAddress((void**)&pc,   g_pc);
    cudaGetSymbolAddress((void**)&pcx,  g_pcx);
    cudaGetSymbolAddress((void**)&t1h,  g_t1h);
    cudaGetSymbolAddress((void**)&yh,   g_yh);
    cudaGetSymbolAddress((void**)&hdnh, g_hdnh);
    cudaGetSymbolAddress((void**)&xnh,  g_xnh);
    cudaGetSymbolAddress((void**)&embh, g_embh);
    cudaGetSymbolAddress((void**)&pwh,  g_pwh);
    cudaGetSymbolAddress((void**)&w1h,  g_w1h);
    cudaGetSymbolAddress((void**)&w2h,  g_w2h);
    cudaGetSymbolAddress((void**)&dnh,  g_dnh);
    cudaGetSymbolAddress((void**)&uph,  g_uph);

    cudaFuncSetAttribute(gemm_h<0>, cudaFuncAttributeMaxDynamicSharedMemorySize, GEMM_SMEM);
    cudaFuncSetAttribute(gemm_h<1>, cudaFuncAttributeMaxDynamicSharedMemorySize, GEMM_SMEM);
    cudaFuncSetAttribute(gemm_h<2>, cudaFuncAttributeMaxDynamicSharedMemorySize, GEMM_SMEM);
    cudaFuncSetAttribute(gemm_h<3>, cudaFuncAttributeMaxDynamicSharedMemorySize, GEMM_SMEM);
    cudaFuncSetAttribute(w1w2glu_k, cudaFuncAttributeMaxDynamicSharedMemorySize, DUAL_SMEM);

    const int egrid = (BLD + 255) / 256;

    {
        int n;
        n = Vn * Dn / 4;        f2h_k<<<(n + 255) / 256, 256>>>(emb,     embh, n);
        n = NLn * Dn * Dn / 4;  f2h_k<<<(n + 255) / 256, 256>>>(pconv_w, pwh,  n);
        n = NLn * Dn * Dn / 4;  f2h_k<<<(n + 255) / 256, 256>>>(w1,      w1h,  n);
        n = NLn * Dn * Dn / 4;  f2h_k<<<(n + 255) / 256, 256>>>(w2,      w2h,  n);
        n = NLn * Hn * Dn / 4;  f2h_k<<<(n + 255) / 256, 256>>>(down_w,  dnh,  n);
        n = NLn * Dn * Hn / 4;  f2h_k<<<(n + 255) / 256, 256>>>(up_w,    uph,  n);
    }

    embed_rope_k<<<egrid, 256>>>(tokens, emb, x);

    for (int i = 0; i < NLn; i++) {
        int dil = 1 << (i % 3);
        rmsnorm_k<<<BLn, 256>>>(x, norm_w + i * Dn, xn, nullptr);
        dconv_k<<<egrid, 256>>>(xn, dconv_w + (size_t)i * Dn * Kn,
                                dconv_b + i * Dn, t1h, dil);
        recur_part_k<<<Bn * CHK, An>>>(xn, alpha + i * An, beta + i * An, pc);
        recur_scan_k<<<1, 256>>>(pc, alpha + i * An, pcx);
        recur_apply_k<<<Bn * CHK, An>>>(xn, alpha + i * An, beta + i * An, pcx, xs);

        dim3 gpw(Dn / 128, BLn / 128);  // (4, 32)
        gemm_h<3><<<gpw, 256, GEMM_SMEM>>>(
            t1h, pwh + (size_t)i * Dn * Dn, pconv_b + i * Dn,
            xs, xn, y, yh, BLn, Dn, Dn);

        w1w2glu_k<<<gpw, 256, DUAL_SMEM>>>(
            yh, w1h + (size_t)i * Dn * Dn, w2h + (size_t)i * Dn * Dn,
            b1 + i * Dn, b2 + i * Dn, y, yh);

        dim3 gdn(Hn / 128, BLn / 128);  // (1, 32)
        gemm_h<1><<<gdn, 256, GEMM_SMEM>>>(
            yh, dnh + (size_t)i * Hn * Dn, down_b + i * Hn,
            nullptr, nullptr, nullptr, hdnh, BLn, Hn, Dn);

        gemm_h<2><<<gpw, 256, GEMM_SMEM>>>(
            hdnh, uph + (size_t)i * Dn * Hn, up_b + i * Dn,
            y, nullptr, x, nullptr, BLn, Dn, Hn);
    }

    rmsnorm_k<<<BLn, 256>>>(x, fnw, nullptr, xnh);
    dim3 gl((Vn + 127) / 128, BLn / 128);  // (393, 32)
    gemm_h<0><<<gl, 256, GEMM_SMEM>>>(
        xnh, embh, nullptr, nullptr, nullptr, out, nullptr, BLn, Vn, Dn);
}